// round 12
// baseline (speedup 1.0000x reference)
#include <cuda_runtime.h>
#include <cstdint>

// Problem constants
#define NV 128   // vocab
#define NE 64    // embed
#define NH 128   // hidden
#define NC 12    // classes
#define NB 2048  // batch
#define NT 256   // timesteps
#define MB 16    // batch tile per block (one warp per batch)
#define NTHR 512
#define THRESH 0.9995f
#define FULL 0xFFFFFFFFu

// 0.8^n constants
#define P8_1 0.8f
#define P8_2 0.64f
#define P8_4 0.4096f
#define P8_8 0.16777216f
#define P8_16 0.028147497671065608f
#define P8_32 0.0007922816251426434f

// Scratch (device globals: no allocation allowed)
__device__ float g_Q[NV * NH];  // written only on the (rare) tier-1+ path
__device__ float g_M[NV];       // row max of Q (always published)
__device__ unsigned g_cnt1;     // epoch barrier #1 (zero-init)
__device__ unsigned g_cnt2;     // epoch barrier #2, tier-1+ only (zero-init)

__device__ __forceinline__ void epoch_barrier(unsigned* cnt, int tid) {
    // writers must have done __syncthreads() before calling (release via
    // tid0 fence; acquire via tid0 fence + __syncthreads after).
    if (tid == 0) {
        __threadfence();
        const unsigned old = atomicAdd(cnt, 1u);
        const unsigned target = ((old >> 7) + 1u) << 7;  // 128 blocks/epoch
        volatile unsigned* pc = cnt;
        while (*pc < target) {
        }
        __threadfence();
    }
    __syncthreads();
}

__global__ __launch_bounds__(NTHR, 1) void snn_fused_kernel(
    const int* __restrict__ ids, const float* __restrict__ emb,
    const float* __restrict__ W_in, const float* __restrict__ b_in,
    const float* __restrict__ W_lif, const float* __restrict__ b_lif,
    const float* __restrict__ W_cls, const float* __restrict__ b_cls,
    float* __restrict__ out) {
    __shared__ __align__(16) float psh[NH];
    __shared__ __align__(16) float qsh[NH];
    __shared__ float wmax[MB];
    __shared__ __align__(16) float Ms[NV];
    __shared__ int idsh[MB * NT];  // replay-only ids staging

    const int tid = threadIdx.x;
    const int lane = tid & 31;
    const int warp = tid >> 5;  // warp == batch within tile (0..15)
    const int v = blockIdx.x;   // vocab row this block prepares (NV == grid)
    const int b0 = blockIdx.x * MB;
    const int h4 = lane * 4;

    // ============ prefetch EVERYTHING (one MLP window) ============
    const float e0 = __ldg(emb + v * NE + lane);
    const float e1 = __ldg(emb + v * NE + 32 + lane);
    float wi0[8], wi1[8];
    float4 wv[8];
#pragma unroll
    for (int r = 0; r < 8; r++) {
        const int h = warp * 8 + r;
        wi0[r] = __ldg(W_in + h * NE + lane);
        wi1[r] = __ldg(W_in + h * NE + 32 + lane);
        wv[r] = __ldg((const float4*)(W_lif + h * NH + h4));
    }
    const float bin = (lane < 8) ? __ldg(b_in + warp * 8 + lane) : 0.f;
    const float bl0 = (lane < 8) ? __ldg(b_lif + warp * 8 + lane) : 0.f;
    float b1[4];
#pragma unroll
    for (int j = 0; j < 4; j++) b1[j] = __ldg(b_lif + NH + h4 + j);
    const float bc = (lane < NC) ? __ldg(b_cls + lane) : 0.f;

    // ============ prep: P = emb[v]@W_in^T + b_in ============
    {
        float pr[8];
#pragma unroll
        for (int r = 0; r < 8; r++) pr[r] = fmaf(wi0[r], e0, wi1[r] * e1);
#pragma unroll
        for (int r = 0; r < 8; r++) {
#pragma unroll
            for (int d = 16; d > 0; d >>= 1)
                pr[r] += __shfl_xor_sync(FULL, pr[r], d);
            if (lane == r) psh[warp * 8 + r] = pr[r] + bin;
        }
    }
    __syncthreads();

    // ============ prep: Q[v,h] = 0.2*(P . W_lif0[h,:] + b_lif0[h]) ========
    // Results land in SMEM only (qsh); g_Q is written on tier-1+ only.
    {
        const float4 pv = *(const float4*)(psh + h4);
        float qr[8];
#pragma unroll
        for (int r = 0; r < 8; r++)
            qr[r] = fmaf(wv[r].x, pv.x,
                         fmaf(wv[r].y, pv.y,
                              fmaf(wv[r].z, pv.z, wv[r].w * pv.w)));
        float qmine = -1e30f;
#pragma unroll
        for (int r = 0; r < 8; r++) {
#pragma unroll
            for (int d = 16; d > 0; d >>= 1)
                qr[r] += __shfl_xor_sync(FULL, qr[r], d);
            if (lane == r) {
                const float qq = 0.2f * (qr[r] + bl0);
                qsh[warp * 8 + r] = qq;
                qmine = qq;
            }
        }
        // warp row-max (non-writer lanes hold -inf)
#pragma unroll
        for (int d = 16; d > 0; d >>= 1)
            qmine = fmaxf(qmine, __shfl_xor_sync(FULL, qmine, d));
        if (lane == 0) wmax[warp] = qmine;
    }
    __syncthreads();
    // tid0 publishes ONE float; its own fence covers it (no STG drain).
    if (tid == 0) {
        float m = wmax[0];
#pragma unroll
        for (int w = 1; w < MB; w++) m = fmaxf(m, wmax[w]);
        g_M[v] = m;
    }
    epoch_barrier(&g_cnt1, tid);

    // ============ tier 0: global no-spike certificate ============
    // u_t <= sum_j 0.8^j max_v M[v] <= 5*max(M*,0) for every batch/step.
    float gm;
    {
        const float m0 = __ldg(g_M + lane);
        const float m1 = __ldg(g_M + lane + 32);
        const float m2 = __ldg(g_M + lane + 64);
        const float m3 = __ldg(g_M + lane + 96);
        gm = fmaxf(fmaxf(m0, m1), fmaxf(m2, m3));
#pragma unroll
        for (int d = 16; d > 0; d >>= 1)
            gm = fmaxf(gm, __shfl_xor_sync(FULL, gm, d));
    }
    const bool bias_safe = __all_sync(
        FULL, (0.2f * b1[0] < 0.19999f) && (0.2f * b1[1] < 0.19999f) &&
                  (0.2f * b1[2] < 0.19999f) && (0.2f * b1[3] < 0.19999f));
    const int b = b0 + warp;

    // Globally uniform decision: every block takes the same branch.
    if (bias_safe && 5.0f * fmaxf(gm, 0.f) < THRESH) {
        // no layer-0 spike possible anywhere -> acc == 0 -> logits = b_cls
        if (lane < NC) out[b * NC + lane] = bc;
        return;
    }

    // ============ tier 1+: publish g_Q, then scan/replay (exact) ==========
    if (tid < NH) g_Q[v * NH + tid] = qsh[tid];  // one coalesced 512B store
    __syncthreads();
    epoch_barrier(&g_cnt2, tid);  // all blocks' g_Q visible past this point

    if (tid < NV / 4) ((float4*)Ms)[tid] = ((const float4*)g_M)[tid];
    int myid[8];
#pragma unroll
    for (int c = 0; c < 8; c++)
        myid[c] = __ldg(ids + b * NT + c * 32 + lane);
    __syncthreads();

    // phase 1: carry-independent chunk scans
    float mxs[8], s31[8];
#pragma unroll
    for (int c = 0; c < 8; c++) {
        float s = Ms[myid[c]];
        float o;
        o = __shfl_up_sync(FULL, s, 1);
        if (lane >= 1) s = fmaf(P8_1, o, s);
        o = __shfl_up_sync(FULL, s, 2);
        if (lane >= 2) s = fmaf(P8_2, o, s);
        o = __shfl_up_sync(FULL, s, 4);
        if (lane >= 4) s = fmaf(P8_4, o, s);
        o = __shfl_up_sync(FULL, s, 8);
        if (lane >= 8) s = fmaf(P8_8, o, s);
        o = __shfl_up_sync(FULL, s, 16);
        if (lane >= 16) s = fmaf(P8_16, o, s);
        float m = s;
#pragma unroll
        for (int d = 16; d > 0; d >>= 1)
            m = fmaxf(m, __shfl_xor_sync(FULL, m, d));
        mxs[c] = m;
        s31[c] = __shfl_sync(FULL, s, 31);
    }

    // phase 2: serial carry + (rare) exact replay
    const float* W1 = W_lif + NH * NH;
    float v0[4] = {0.f, 0.f, 0.f, 0.f};
    float v1[4] = {0.f, 0.f, 0.f, 0.f};
    float acc[4] = {0.f, 0.f, 0.f, 0.f};
    int tck = 0;
    float u = 0.f;
    bool staged = false;

    for (int c = 0; c < 8; c++) {
        const float bnd = fmaf(0.8f, fmaxf(u, 0.f), mxs[c]);
        if (!bias_safe || bnd >= THRESH) {
            if (!staged) {
#pragma unroll
                for (int cc = 0; cc < 8; cc++)
                    idsh[warp * NT + cc * 32 + lane] = myid[cc];
                __syncwarp();
                staged = true;
            }
            const int tend = (c + 1) * 32;
            for (int t = tck; t < tend; t++) {
                const int id = idsh[warp * NT + t];
                const float4 q = __ldg((const float4*)(g_Q + id * NH + h4));
                float n0 = fmaf(0.8f, v0[0], q.x);
                float n1 = fmaf(0.8f, v0[1], q.y);
                float n2 = fmaf(0.8f, v0[2], q.z);
                float n3 = fmaf(0.8f, v0[3], q.w);
                unsigned bm[4];
                bm[0] = __ballot_sync(FULL, n0 >= 1.0f);
                bm[1] = __ballot_sync(FULL, n1 >= 1.0f);
                bm[2] = __ballot_sync(FULL, n2 >= 1.0f);
                bm[3] = __ballot_sync(FULL, n3 >= 1.0f);
                v0[0] = (n0 >= 1.0f) ? 0.f : n0;
                v0[1] = (n1 >= 1.0f) ? 0.f : n1;
                v0[2] = (n2 >= 1.0f) ? 0.f : n2;
                v0[3] = (n3 >= 1.0f) ? 0.f : n3;

                float cur[4] = {0.f, 0.f, 0.f, 0.f};
#pragma unroll
                for (int w = 0; w < 4; w++) {
                    unsigned mm = bm[w];
                    while (mm) {
                        const int l = __ffs(mm) - 1;
                        mm &= mm - 1;
                        const float* col = W1 + (l * 4 + w);
                        cur[0] += __ldg(col + (h4 + 0) * NH);
                        cur[1] += __ldg(col + (h4 + 1) * NH);
                        cur[2] += __ldg(col + (h4 + 2) * NH);
                        cur[3] += __ldg(col + (h4 + 3) * NH);
                    }
                }
#pragma unroll
                for (int j = 0; j < 4; j++) {
                    const float cc2 = cur[j] + b1[j];
                    const float vv = 0.8f * v1[j] + 0.2f * cc2;
                    const bool s = (vv >= 1.0f);
                    acc[j] += s ? 1.f : 0.f;
                    v1[j] = s ? 0.f : vv;
                }
            }
            tck = tend;
            float w = fmaxf(fmaxf(v0[0], v0[1]), fmaxf(v0[2], v0[3]));
#pragma unroll
            for (int d = 16; d > 0; d >>= 1)
                w = fmaxf(w, __shfl_xor_sync(FULL, w, d));
            u = w;
        } else {
            u = fmaf(P8_32, u, s31[c]);
        }
    }

    // epilogue
    if (tck == 0) {
        if (lane < NC) out[b * NC + lane] = bc;
    } else {
        const float invT = 1.0f / (float)NT;
#pragma unroll
        for (int cc = 0; cc < NC; cc++) {
            const float* wc = W_cls + cc * NH + h4;
            float p = acc[0] * __ldg(wc + 0) + acc[1] * __ldg(wc + 1) +
                      acc[2] * __ldg(wc + 2) + acc[3] * __ldg(wc + 3);
#pragma unroll
            for (int d = 16; d > 0; d >>= 1)
                p += __shfl_xor_sync(FULL, p, d);
            if (lane == 0) out[b * NC + cc] = p * invT + b_cls[cc];
        }
    }
}

// ---------------------------------------------------------------------------
// Host launcher (graph-capturable: ONE kernel launch)
// Input order: ids, emb, W_in, b_in, W_lif, b_lif, W_rec(unused), W_cls, b_cls
// ---------------------------------------------------------------------------
extern "C" void kernel_launch(void* const* d_in, const int* in_sizes, int n_in,
                              void* d_out, int out_size) {
    const int* ids = (const int*)d_in[0];
    const float* emb = (const float*)d_in[1];
    const float* W_in = (const float*)d_in[2];
    const float* b_in = (const float*)d_in[3];
    const float* W_lif = (const float*)d_in[4];
    const float* b_lif = (const float*)d_in[5];
    const float* W_cls = (const float*)d_in[7];
    const float* b_cls = (const float*)d_in[8];
    float* out = (float*)d_out;

    snn_fused_kernel<<<NB / MB, NTHR>>>(ids, emb, W_in, b_in, W_lif, b_lif,
                                        W_cls, b_cls, out);
}